// round 15
// baseline (speedup 1.0000x reference)
#include <cuda_runtime.h>

// InducingLocationsSpatialTransform: bilinear affine warp
// X: (N=512, H=64, W=64, C=32) f32, theta: (N, 6) f32 -> out: (N,H,W,C) f32
//
// R14 + fused heavy path: when BOTH pixels of the k-pair have any in-range
// lane (warp-uniform vote; the dominant non-zero case since in/out status is
// spatially coherent), all 8 gather loads issue back-to-back (MLP=8) before
// any blending. Zero shortcut: clipped-corner weights cancel exactly to 0
// for out-of-range pixels, so all-out warps store zeros with no loads.

#define N_ 512
#define H_ 64
#define W_ 64
#define C_ 32
#define HW_ (H_ * W_)

__global__ __launch_bounds__(512, 4) void st_kernel(
    const float* __restrict__ X,
    const float* __restrict__ theta,
    float* __restrict__ out)
{
    const unsigned FULL = 0xffffffffu;
    int tid = blockIdx.x * 512 + threadIdx.x;
    int q   = tid >> 3;        // 4-pixel group id
    int cg  = tid & 7;         // float4 group within the 32 channels

    int pid0 = q << 2;
    int n = pid0 >> 12;
    int p = pid0 & 4095;
    int y = p >> 6;
    int x = p & 63;

    const float* th = theta + n * 6;
    float t0 = __ldg(th + 0), t1 = __ldg(th + 1), t2 = __ldg(th + 2);
    float t3 = __ldg(th + 3), t4 = __ldg(th + 4), t5 = __ldg(th + 5);

    const float step = 2.0f / 63.0f;
    float xt = -1.0f + (float)x * step;
    float yt = -1.0f + (float)y * step;

    float gx0 = (float)W_ * ((t0 * xt + t1 * yt + t2) + 1.0f) * 0.5f;
    float gy0 = (float)H_ * ((t3 * xt + t4 * yt + t5) + 1.0f) * 0.5f;
    float dgx = (0.5f * (float)W_ * step) * t0;
    float dgy = (0.5f * (float)H_ * step) * t3;

    const float4* S = (const float4*)(X + (size_t)n * (HW_ * C_));
    float4* O = (float4*)out + (size_t)pid0 * 8;

    const float4 zero4 = make_float4(0.f, 0.f, 0.f, 0.f);

    #pragma unroll
    for (int k = 0; k < 4; k += 2) {
        float gxa = gx0 + (float)k * dgx;
        float gya = gy0 + (float)k * dgy;
        float gxb = gxa + dgx;
        float gyb = gya + dgy;

        float fxa = floorf(gxa), fya = floorf(gya);
        float fxb = floorf(gxb), fyb = floorf(gyb);

        bool inA = (fxa >= 0.f) & (fxa <= 62.f) & (fya >= 0.f) & (fya <= 62.f);
        bool inB = (fxb >= 0.f) & (fxb <= 62.f) & (fyb >= 0.f) & (fyb <= 62.f);

        bool anyA = __any_sync(FULL, inA);
        bool anyB = __any_sync(FULL, inB);

        if (anyA & anyB) {
            // ---- fused heavy path: 8 batched loads (MLP=8) ----
            int ax0 = min(max((int)fxa,     0), W_ - 1);
            int ax1 = min(max((int)fxa + 1, 0), W_ - 1);
            int ay0 = min(max((int)fya,     0), H_ - 1);
            int ay1 = min(max((int)fya + 1, 0), H_ - 1);
            int bx0 = min(max((int)fxb,     0), W_ - 1);
            int bx1 = min(max((int)fxb + 1, 0), W_ - 1);
            int by0 = min(max((int)fyb,     0), H_ - 1);
            int by1 = min(max((int)fyb + 1, 0), H_ - 1);

            float4 va0 = __ldg(&S[(ay0 * W_ + ax0) * 8 + cg]);
            float4 vb0 = __ldg(&S[(ay1 * W_ + ax0) * 8 + cg]);
            float4 vc0 = __ldg(&S[(ay0 * W_ + ax1) * 8 + cg]);
            float4 vd0 = __ldg(&S[(ay1 * W_ + ax1) * 8 + cg]);
            float4 va1 = __ldg(&S[(by0 * W_ + bx0) * 8 + cg]);
            float4 vb1 = __ldg(&S[(by1 * W_ + bx0) * 8 + cg]);
            float4 vc1 = __ldg(&S[(by0 * W_ + bx1) * 8 + cg]);
            float4 vd1 = __ldg(&S[(by1 * W_ + bx1) * 8 + cg]);

            float wa0 = ((float)ax1 - gxa) * ((float)ay1 - gya);
            float wb0 = ((float)ax1 - gxa) * (gya - (float)ay0);
            float wc0 = (gxa - (float)ax0) * ((float)ay1 - gya);
            float wd0 = (gxa - (float)ax0) * (gya - (float)ay0);
            float wa1 = ((float)bx1 - gxb) * ((float)by1 - gyb);
            float wb1 = ((float)bx1 - gxb) * (gyb - (float)by0);
            float wc1 = (gxb - (float)bx0) * ((float)by1 - gyb);
            float wd1 = (gxb - (float)bx0) * (gyb - (float)by0);

            float4 r0, r1;
            r0.x = wa0 * va0.x + wb0 * vb0.x + wc0 * vc0.x + wd0 * vd0.x;
            r0.y = wa0 * va0.y + wb0 * vb0.y + wc0 * vc0.y + wd0 * vd0.y;
            r0.z = wa0 * va0.z + wb0 * vb0.z + wc0 * vc0.z + wd0 * vd0.z;
            r0.w = wa0 * va0.w + wb0 * vb0.w + wc0 * vc0.w + wd0 * vd0.w;
            r1.x = wa1 * va1.x + wb1 * vb1.x + wc1 * vc1.x + wd1 * vd1.x;
            r1.y = wa1 * va1.y + wb1 * vb1.y + wc1 * vc1.y + wd1 * vd1.y;
            r1.z = wa1 * va1.z + wb1 * vb1.z + wc1 * vc1.z + wd1 * vd1.z;
            r1.w = wa1 * va1.w + wb1 * vb1.w + wc1 * vc1.w + wd1 * vd1.w;

            __stcs(&O[k * 8 + cg],       r0);
            __stcs(&O[(k + 1) * 8 + cg], r1);
        } else {
            // ---- boundary / zero paths (warp-uniform) ----
            if (anyA) {
                int ax0 = min(max((int)fxa,     0), W_ - 1);
                int ax1 = min(max((int)fxa + 1, 0), W_ - 1);
                int ay0 = min(max((int)fya,     0), H_ - 1);
                int ay1 = min(max((int)fya + 1, 0), H_ - 1);

                float4 va = __ldg(&S[(ay0 * W_ + ax0) * 8 + cg]);
                float4 vb = __ldg(&S[(ay1 * W_ + ax0) * 8 + cg]);
                float4 vc = __ldg(&S[(ay0 * W_ + ax1) * 8 + cg]);
                float4 vd = __ldg(&S[(ay1 * W_ + ax1) * 8 + cg]);

                float wa = ((float)ax1 - gxa) * ((float)ay1 - gya);
                float wb = ((float)ax1 - gxa) * (gya - (float)ay0);
                float wc = (gxa - (float)ax0) * ((float)ay1 - gya);
                float wd = (gxa - (float)ax0) * (gya - (float)ay0);

                float4 r;
                r.x = wa * va.x + wb * vb.x + wc * vc.x + wd * vd.x;
                r.y = wa * va.y + wb * vb.y + wc * vc.y + wd * vd.y;
                r.z = wa * va.z + wb * vb.z + wc * vc.z + wd * vd.z;
                r.w = wa * va.w + wb * vb.w + wc * vc.w + wd * vd.w;
                __stcs(&O[k * 8 + cg], r);
            } else {
                __stcs(&O[k * 8 + cg], zero4);
            }

            if (anyB) {
                int bx0 = min(max((int)fxb,     0), W_ - 1);
                int bx1 = min(max((int)fxb + 1, 0), W_ - 1);
                int by0 = min(max((int)fyb,     0), H_ - 1);
                int by1 = min(max((int)fyb + 1, 0), H_ - 1);

                float4 va = __ldg(&S[(by0 * W_ + bx0) * 8 + cg]);
                float4 vb = __ldg(&S[(by1 * W_ + bx0) * 8 + cg]);
                float4 vc = __ldg(&S[(by0 * W_ + bx1) * 8 + cg]);
                float4 vd = __ldg(&S[(by1 * W_ + bx1) * 8 + cg]);

                float wa = ((float)bx1 - gxb) * ((float)by1 - gyb);
                float wb = ((float)bx1 - gxb) * (gyb - (float)by0);
                float wc = (gxb - (float)bx0) * ((float)by1 - gyb);
                float wd = (gxb - (float)bx0) * (gyb - (float)by0);

                float4 r;
                r.x = wa * va.x + wb * vb.x + wc * vc.x + wd * vd.x;
                r.y = wa * va.y + wb * vb.y + wc * vc.y + wd * vd.y;
                r.z = wa * va.z + wb * vb.z + wc * vc.z + wd * vd.z;
                r.w = wa * va.w + wb * vb.w + wc * vc.w + wd * vd.w;
                __stcs(&O[(k + 1) * 8 + cg], r);
            } else {
                __stcs(&O[(k + 1) * 8 + cg], zero4);
            }
        }
    }
}

extern "C" void kernel_launch(void* const* d_in, const int* in_sizes, int n_in,
                              void* d_out, int out_size)
{
    const float* X     = (const float*)d_in[0];
    const float* theta = (const float*)d_in[1];
    float* out         = (float*)d_out;

    int threads = 512;
    int blocks = (N_ * HW_ * 2) / threads;   // 8192
    st_kernel<<<blocks, threads>>>(X, theta, out);
}

// round 16
// speedup vs baseline: 1.3658x; 1.3658x over previous
#include <cuda_runtime.h>

// InducingLocationsSpatialTransform: bilinear affine warp
// X: (N=512, H=64, W=64, C=32) f32, theta: (N, 6) f32 -> out: (N,H,W,C) f32
//
// R14 logic (per-pixel warp-uniform zero votes + streaming stores) with
// 256-thread CTAs: finer scheduling granularity smooths the CTA-duration
// imbalance that zero-skipping creates (all-out CTAs finish ~3x faster),
// recovering achieved occupancy lost to backfill quantization.
// Zero shortcut validity: clipped-corner weights cancel exactly to 0 when
// floor(gx) or floor(gy) is outside [0,62].

#define N_ 512
#define H_ 64
#define W_ 64
#define C_ 32
#define HW_ (H_ * W_)

__global__ __launch_bounds__(256, 8) void st_kernel(
    const float* __restrict__ X,
    const float* __restrict__ theta,
    float* __restrict__ out)
{
    const unsigned FULL = 0xffffffffu;
    int tid = blockIdx.x * 256 + threadIdx.x;
    int q   = tid >> 3;        // 4-pixel group id
    int cg  = tid & 7;         // float4 group within the 32 channels

    int pid0 = q << 2;
    int n = pid0 >> 12;
    int p = pid0 & 4095;
    int y = p >> 6;
    int x = p & 63;

    const float* th = theta + n * 6;
    float t0 = __ldg(th + 0), t1 = __ldg(th + 1), t2 = __ldg(th + 2);
    float t3 = __ldg(th + 3), t4 = __ldg(th + 4), t5 = __ldg(th + 5);

    const float step = 2.0f / 63.0f;
    float xt = -1.0f + (float)x * step;
    float yt = -1.0f + (float)y * step;

    float gx0 = (float)W_ * ((t0 * xt + t1 * yt + t2) + 1.0f) * 0.5f;
    float gy0 = (float)H_ * ((t3 * xt + t4 * yt + t5) + 1.0f) * 0.5f;
    float dgx = (0.5f * (float)W_ * step) * t0;
    float dgy = (0.5f * (float)H_ * step) * t3;

    // Fold the channel-group offset into the base pointer: one IMAD less
    // per gather address.
    const float4* Sc = (const float4*)(X + (size_t)n * (HW_ * C_)) + cg;
    float4* O = (float4*)out + (size_t)pid0 * 8;

    const float4 zero4 = make_float4(0.f, 0.f, 0.f, 0.f);

    #pragma unroll
    for (int k = 0; k < 4; k += 2) {
        float gxa = gx0 + (float)k * dgx;
        float gya = gy0 + (float)k * dgy;
        float gxb = gxa + dgx;
        float gyb = gya + dgy;

        float fxa = floorf(gxa), fya = floorf(gya);
        float fxb = floorf(gxb), fyb = floorf(gyb);

        bool inA = (fxa >= 0.f) & (fxa <= 62.f) & (fya >= 0.f) & (fya <= 62.f);
        bool inB = (fxb >= 0.f) & (fxb <= 62.f) & (fyb >= 0.f) & (fyb <= 62.f);

        bool anyA = __any_sync(FULL, inA);
        bool anyB = __any_sync(FULL, inB);

        // ---- pixel a ----
        if (anyA) {
            int ax0 = min(max((int)fxa,     0), W_ - 1);
            int ax1 = min(max((int)fxa + 1, 0), W_ - 1);
            int ay0 = min(max((int)fya,     0), H_ - 1);
            int ay1 = min(max((int)fya + 1, 0), H_ - 1);

            float4 va = __ldg(&Sc[(ay0 * W_ + ax0) * 8]);
            float4 vb = __ldg(&Sc[(ay1 * W_ + ax0) * 8]);
            float4 vc = __ldg(&Sc[(ay0 * W_ + ax1) * 8]);
            float4 vd = __ldg(&Sc[(ay1 * W_ + ax1) * 8]);

            float wa = ((float)ax1 - gxa) * ((float)ay1 - gya);
            float wb = ((float)ax1 - gxa) * (gya - (float)ay0);
            float wc = (gxa - (float)ax0) * ((float)ay1 - gya);
            float wd = (gxa - (float)ax0) * (gya - (float)ay0);

            float4 r;
            r.x = wa * va.x + wb * vb.x + wc * vc.x + wd * vd.x;
            r.y = wa * va.y + wb * vb.y + wc * vc.y + wd * vd.y;
            r.z = wa * va.z + wb * vb.z + wc * vc.z + wd * vd.z;
            r.w = wa * va.w + wb * vb.w + wc * vc.w + wd * vd.w;
            __stcs(&O[k * 8 + cg], r);
        } else {
            __stcs(&O[k * 8 + cg], zero4);
        }

        // ---- pixel b ----
        if (anyB) {
            int bx0 = min(max((int)fxb,     0), W_ - 1);
            int bx1 = min(max((int)fxb + 1, 0), W_ - 1);
            int by0 = min(max((int)fyb,     0), H_ - 1);
            int by1 = min(max((int)fyb + 1, 0), H_ - 1);

            float4 va = __ldg(&Sc[(by0 * W_ + bx0) * 8]);
            float4 vb = __ldg(&Sc[(by1 * W_ + bx0) * 8]);
            float4 vc = __ldg(&Sc[(by0 * W_ + bx1) * 8]);
            float4 vd = __ldg(&Sc[(by1 * W_ + bx1) * 8]);

            float wa = ((float)bx1 - gxb) * ((float)by1 - gyb);
            float wb = ((float)bx1 - gxb) * (gyb - (float)by0);
            float wc = (gxb - (float)bx0) * ((float)by1 - gyb);
            float wd = (gxb - (float)bx0) * (gyb - (float)by0);

            float4 r;
            r.x = wa * va.x + wb * vb.x + wc * vc.x + wd * vd.x;
            r.y = wa * va.y + wb * vb.y + wc * vc.y + wd * vd.y;
            r.z = wa * va.z + wb * vb.z + wc * vc.z + wd * vd.z;
            r.w = wa * va.w + wb * vb.w + wc * vc.w + wd * vd.w;
            __stcs(&O[(k + 1) * 8 + cg], r);
        } else {
            __stcs(&O[(k + 1) * 8 + cg], zero4);
        }
    }
}

extern "C" void kernel_launch(void* const* d_in, const int* in_sizes, int n_in,
                              void* d_out, int out_size)
{
    const float* X     = (const float*)d_in[0];
    const float* theta = (const float*)d_in[1];
    float* out         = (float*)d_out;

    int threads = 256;
    int blocks = (N_ * HW_ * 2) / threads;   // 16384
    st_kernel<<<blocks, threads>>>(X, theta, out);
}